// round 5
// baseline (speedup 1.0000x reference)
#include <cuda_runtime.h>
#include <cuda_bf16.h>

#define BB 2048
#define TT 512
#define KK 32
#define NEG_INF (-3.4e38f)
#define NCTA (148 * 13)

__device__ unsigned g_ctrV;
__device__ unsigned g_ctrF;

__global__ void crf_init()
{
    g_ctrV = 0u;
    g_ctrF = 0u;
}

// CTA = 2 warps with fully decoupled roles and private work queues:
//   warp 0: Viterbi recurrence + backtrace + tags + best_score
//   warp 1: forward logsumexp recurrence + gold score + log_likelihood
// No per-step inter-warp communication; smem regions are disjoint.
__global__ __launch_bounds__(64, 13) void crf_kernel(
    const float* __restrict__ pot,     // [B,T,K]
    const float* __restrict__ trans,   // [K,K]
    const int*   __restrict__ lens,    // [B]
    const int*   __restrict__ tagidx,  // [B,T]
    float*       __restrict__ out)     // [B*T] tags, [B] best, [B] loglik
{
    const int lane = threadIdx.x & 31;
    const int wid  = threadIdx.x >> 5;

    // warp-0 private
    __shared__ unsigned char bp_sm[TT * KK];
    __shared__ __align__(16) float aVbuf[2][KK];
    __shared__ __align__(16) unsigned char tags_sm[TT];
    // warp-1 private
    __shared__ __align__(16) float pXbuf[2][KK];
    __shared__ __align__(16) float aFbuf[2][KK];

    if (wid == 0) {
        // ================= Viterbi warp =================
        float tc[KK];
#pragma unroll
        for (int j = 0; j < KK; j++) tc[j] = trans[j * KK + lane];

        for (;;) {
            unsigned b = 0;
            if (lane == 0) b = atomicAdd(&g_ctrV, 1u);
            b = __shfl_sync(0xffffffffu, b, 0);
            if (b >= BB) break;

            const int len = lens[b];
            const float* pb = pot + (size_t)b * (TT * KK);

            float aV = pb[lane];
            float q0 = pb[1 * KK + lane];
            float q1 = pb[2 * KK + lane];
            float q2 = pb[3 * KK + lane];
            float q3 = pb[4 * KK + lane];

            auto vstep = [&](float pt, int t, int buf) {
                aVbuf[buf][lane] = aV;
                __syncwarp();
                const float4* a4 = (const float4*)aVbuf[buf];
                float m0 = NEG_INF, m1 = NEG_INF, m2 = NEG_INF, m3 = NEG_INF;
                int   i0 = 0, i1 = 0, i2 = 0, i3 = 0;
#pragma unroll
                for (int q = 0; q < 8; q++) {
                    float4 a = a4[q];
                    float v0 = a.x + tc[4*q+0]; if (v0 > m0) { m0 = v0; i0 = 4*q+0; }
                    float v1 = a.y + tc[4*q+1]; if (v1 > m1) { m1 = v1; i1 = 4*q+1; }
                    float v2 = a.z + tc[4*q+2]; if (v2 > m2) { m2 = v2; i2 = 4*q+2; }
                    float v3 = a.w + tc[4*q+3]; if (v3 > m3) { m3 = v3; i3 = 4*q+3; }
                }
                float best = m0; int arg = i0;
                if (m1 > best || (m1 == best && i1 < arg)) { best = m1; arg = i1; }
                if (m2 > best || (m2 == best && i2 < arg)) { best = m2; arg = i2; }
                if (m3 > best || (m3 == best && i3 < arg)) { best = m3; arg = i3; }
                bp_sm[t * KK + lane] = (unsigned char)arg;
                aV = pt + best;
            };

            int t = 1;
            for (; t + 3 < len; t += 4) {
                int c4 = min(t + 4, TT - 1), c5 = min(t + 5, TT - 1);
                int c6 = min(t + 6, TT - 1), c7 = min(t + 7, TT - 1);
                float n0 = pb[c4 * KK + lane];
                float n1 = pb[c5 * KK + lane];
                float n2 = pb[c6 * KK + lane];
                float n3 = pb[c7 * KK + lane];
                vstep(q0, t + 0, 1);
                vstep(q1, t + 1, 0);
                vstep(q2, t + 2, 1);
                vstep(q3, t + 3, 0);
                q0 = n0; q1 = n1; q2 = n2; q3 = n3;
            }
            if (t < len) { vstep(q0, t, 1); t++; }
            if (t < len) { vstep(q1, t, 0); t++; }
            if (t < len) { vstep(q2, t, 1); }
            __syncwarp();

            // terminal: best_score + last_tag (first max index)
            float mv = aV;
#pragma unroll
            for (int s = 16; s; s >>= 1)
                mv = fmaxf(mv, __shfl_xor_sync(0xffffffffu, mv, s));
            unsigned msk = __ballot_sync(0xffffffffu, aV == mv);
            int last_tag = __ffs(msk) - 1;

            // fill tags with last_tag (covers padded tail + position len-1)
            unsigned rep = (unsigned)last_tag * 0x01010101u;
#pragma unroll
            for (int w = 0; w < 4; w++)
                ((unsigned*)tags_sm)[w * 32 + lane] = rep;
            __syncwarp();

            if (lane == 0) {
                int tg = last_tag;
                for (int tt = len - 1; tt >= 1; tt--) {
                    tg = bp_sm[tt * KK + tg];
                    tags_sm[tt - 1] = (unsigned char)tg;
                }
            }
            __syncwarp();

            // coalesced tag output (float), 4 x float4 per lane
            float* otags = out + (size_t)b * TT;
#pragma unroll
            for (int c = 0; c < 4; c++) {
                uchar4 u = ((const uchar4*)tags_sm)[c * 32 + lane];
                float4 f = make_float4((float)u.x, (float)u.y, (float)u.z, (float)u.w);
                ((float4*)otags)[c * 32 + lane] = f;
            }

            if (lane == 0)
                out[(size_t)BB * TT + b] = mv;   // best_score
        }
    } else {
        // ================= Forward warp =================
        float ec[KK];
#pragma unroll
        for (int j = 0; j < KK; j++) ec[j] = __expf(trans[j * KK + lane]);

        for (;;) {
            unsigned b = 0;
            if (lane == 0) b = atomicAdd(&g_ctrF, 1u);
            b = __shfl_sync(0xffffffffu, b, 0);
            if (b >= BB) break;

            const int len = lens[b];
            const float* pb = pot + (size_t)b * (TT * KK);

            float aF = pb[lane];
            float mcur = __shfl_sync(0xffffffffu, aF, 0);

            float q0 = pb[1 * KK + lane];
            float q1 = pb[2 * KK + lane];
            float q2 = pb[3 * KK + lane];
            float q3 = pb[4 * KK + lane];

            auto fstep = [&](float pt, int buf) {
                float pexp = __expf(aF - mcur);
                pXbuf[buf][lane] = pexp;
                aFbuf[buf][lane] = aF;
                __syncwarp();
                const float4* p4 = (const float4*)pXbuf[buf];
                float s0 = 0.f, s1 = 0.f, s2 = 0.f, s3 = 0.f;
#pragma unroll
                for (int q = 0; q < 8; q++) {
                    float4 p = p4[q];
                    s0 += p.x * ec[4*q+0];
                    s1 += p.y * ec[4*q+1];
                    s2 += p.z * ec[4*q+2];
                    s3 += p.w * ec[4*q+3];
                }
                float ssum = (s0 + s1) + (s2 + s3);
                aF = pt + (mcur + __logf(ssum));
                mcur = aFbuf[buf][0];   // prev step's aF[0] = next uniform offset
            };

            int t = 1;
            for (; t + 3 < len; t += 4) {
                int c4 = min(t + 4, TT - 1), c5 = min(t + 5, TT - 1);
                int c6 = min(t + 6, TT - 1), c7 = min(t + 7, TT - 1);
                float n0 = pb[c4 * KK + lane];
                float n1 = pb[c5 * KK + lane];
                float n2 = pb[c6 * KK + lane];
                float n3 = pb[c7 * KK + lane];
                fstep(q0, 1);
                fstep(q1, 0);
                fstep(q2, 1);
                fstep(q3, 0);
                q0 = n0; q1 = n1; q2 = n2; q3 = n3;
            }
            if (t < len) { fstep(q0, 1); t++; }
            if (t < len) { fstep(q1, 0); t++; }
            if (t < len) { fstep(q2, 1); }
            __syncwarp();

            // exact final logsumexp
            float mf = aF;
#pragma unroll
            for (int s = 16; s; s >>= 1)
                mf = fmaxf(mf, __shfl_xor_sync(0xffffffffu, mf, s));
            float ex = __expf(aF - mf);
#pragma unroll
            for (int s = 16; s; s >>= 1)
                ex += __shfl_xor_sync(0xffffffffu, ex, s);
            float log_norm = mf + __logf(ex);

            // gold sequence score
            const int* ti = tagidx + (size_t)b * TT;
            float acc = 0.f;
            for (int tt = lane; tt < TT; tt += 32) {
                int tg = ti[tt];
                if (tt < len)
                    acc += pb[tt * KK + tg];
                if (tt < len - 1)
                    acc += trans[tg * KK + ti[tt + 1]];
            }
#pragma unroll
            for (int s = 16; s; s >>= 1)
                acc += __shfl_xor_sync(0xffffffffu, acc, s);

            if (lane == 0)
                out[(size_t)BB * TT + BB + b] = acc - log_norm;   // log_likelihood
        }
    }
}

extern "C" void kernel_launch(void* const* d_in, const int* in_sizes, int n_in,
                              void* d_out, int out_size) {
    const float* pot = nullptr;
    const float* trn = nullptr;
    const int*   len = nullptr;
    const int*   tgi = nullptr;
    for (int i = 0; i < n_in; i++) {
        switch (in_sizes[i]) {
            case 33554432: pot = (const float*)d_in[i]; break;
            case 1024:     trn = (const float*)d_in[i]; break;
            case 2048:     len = (const int*)d_in[i];   break;
            case 1048576:  tgi = (const int*)d_in[i];   break;
            default: break;
        }
    }
    float* out = (float*)d_out;
    crf_init<<<1, 1>>>();
    crf_kernel<<<NCTA, 64>>>(pot, trn, len, tgi, out);
    (void)out_size;
}

// round 7
// speedup vs baseline: 1.5466x; 1.5466x over previous
#include <cuda_runtime.h>
#include <cuda_bf16.h>

#define BB 2048
#define TT 512
#define KK 32
#define NEG_INF (-3.4e38f)
#define NCTA (148 * 13)

__device__ unsigned g_ctr;

__global__ void crf_init() { g_ctr = 0u; }

// One warp per CTA; warp pulls batch items from a global queue and runs BOTH
// recurrences (Viterbi + forward) per item — R4 per-step math, R5 scheduling.
__global__ __launch_bounds__(32) void crf_kernel(
    const float* __restrict__ pot,     // [B,T,K]
    const float* __restrict__ trans,   // [K,K]
    const int*   __restrict__ lens,    // [B]
    const int*   __restrict__ tagidx,  // [B,T]
    float*       __restrict__ out)     // [B*T] tags, [B] best, [B] loglik
{
    const int lane = threadIdx.x;

    __shared__ unsigned char bp_sm[TT * KK];
    __shared__ __align__(16) float aVbuf[2][KK];
    __shared__ __align__(16) float pXbuf[2][KK];
    __shared__ __align__(16) unsigned char tags_sm[TT];

    // transitions column k (coalesced) + exp — loaded once per block
    float tc[KK], ec[KK];
#pragma unroll
    for (int j = 0; j < KK; j++) {
        float v = trans[j * KK + lane];
        tc[j] = v;
        ec[j] = __expf(v);
    }

    for (;;) {
        unsigned b = 0;
        if (lane == 0) b = atomicAdd(&g_ctr, 1u);
        b = __shfl_sync(0xffffffffu, b, 0);
        if (b >= BB) break;

        const int len = lens[b];
        const float* pb = pot + (size_t)b * (TT * KK);

        float aV = pb[lane];
        float aF = aV;
        float mcur = __shfl_sync(0xffffffffu, aF, 0);

        // prefetch ring, depth 4 (rows 1..4 in-bounds, TT=512)
        float q0 = pb[1 * KK + lane];
        float q1 = pb[2 * KK + lane];
        float q2 = pb[3 * KK + lane];
        float q3 = pb[4 * KK + lane];

        auto step = [&](float pt, int t, int buf) {
            float pexp = __expf(aF - mcur);
            aVbuf[buf][lane] = aV;
            pXbuf[buf][lane] = pexp;
            __syncwarp();
            const float4* a4 = (const float4*)aVbuf[buf];
            const float4* p4 = (const float4*)pXbuf[buf];

            float m0 = NEG_INF, m1 = NEG_INF, m2 = NEG_INF, m3 = NEG_INF;
            int   i0 = 0, i1 = 0, i2 = 0, i3 = 0;
            float s0 = 0.f, s1 = 0.f, s2 = 0.f, s3 = 0.f;
#pragma unroll
            for (int q = 0; q < 8; q++) {
                float4 a = a4[q];
                float v0 = a.x + tc[4*q+0]; if (v0 > m0) { m0 = v0; i0 = 4*q+0; }
                float v1 = a.y + tc[4*q+1]; if (v1 > m1) { m1 = v1; i1 = 4*q+1; }
                float v2 = a.z + tc[4*q+2]; if (v2 > m2) { m2 = v2; i2 = 4*q+2; }
                float v3 = a.w + tc[4*q+3]; if (v3 > m3) { m3 = v3; i3 = 4*q+3; }
                float4 p = p4[q];
                s0 += p.x * ec[4*q+0];
                s1 += p.y * ec[4*q+1];
                s2 += p.z * ec[4*q+2];
                s3 += p.w * ec[4*q+3];
            }
            float best = m0; int arg = i0;
            if (m1 > best || (m1 == best && i1 < arg)) { best = m1; arg = i1; }
            if (m2 > best || (m2 == best && i2 < arg)) { best = m2; arg = i2; }
            if (m3 > best || (m3 == best && i3 < arg)) { best = m3; arg = i3; }
            float ssum = (s0 + s1) + (s2 + s3);

            bp_sm[t * KK + lane] = (unsigned char)arg;
            aV = pt + best;
            aF = pt + (mcur + __logf(ssum));
            mcur = __shfl_sync(0xffffffffu, aF, 0);   // uniform offset = new aF lane 0
        };

        int t = 1;
        for (; t + 3 < len; t += 4) {
            int c4 = min(t + 4, TT - 1), c5 = min(t + 5, TT - 1);
            int c6 = min(t + 6, TT - 1), c7 = min(t + 7, TT - 1);
            float n0 = pb[c4 * KK + lane];
            float n1 = pb[c5 * KK + lane];
            float n2 = pb[c6 * KK + lane];
            float n3 = pb[c7 * KK + lane];
            step(q0, t + 0, 1);
            step(q1, t + 1, 0);
            step(q2, t + 2, 1);
            step(q3, t + 3, 0);
            q0 = n0; q1 = n1; q2 = n2; q3 = n3;
        }
        if (t < len) { step(q0, t, 1); t++; }
        if (t < len) { step(q1, t, 0); t++; }
        if (t < len) { step(q2, t, 1); }
        __syncwarp();

        // ---- Viterbi terminal: best_score + last_tag (first max index) ----
        float mv = aV;
#pragma unroll
        for (int s = 16; s; s >>= 1)
            mv = fmaxf(mv, __shfl_xor_sync(0xffffffffu, mv, s));
        unsigned msk = __ballot_sync(0xffffffffu, aV == mv);
        int last_tag = __ffs(msk) - 1;

        // ---- exact final logsumexp ----
        float mf = aF;
#pragma unroll
        for (int s = 16; s; s >>= 1)
            mf = fmaxf(mf, __shfl_xor_sync(0xffffffffu, mf, s));
        float ex = __expf(aF - mf);
#pragma unroll
        for (int s = 16; s; s >>= 1)
            ex += __shfl_xor_sync(0xffffffffu, ex, s);
        float log_norm = mf + __logf(ex);

        // ---- tags: fill with last_tag, then backtrace over smem ----
        unsigned rep = (unsigned)last_tag * 0x01010101u;
#pragma unroll
        for (int w = 0; w < 4; w++)
            ((unsigned*)tags_sm)[w * 32 + lane] = rep;
        __syncwarp();

        if (lane == 0) {
            int tg = last_tag;
            for (int tt = len - 1; tt >= 1; tt--) {
                tg = bp_sm[tt * KK + tg];
                tags_sm[tt - 1] = (unsigned char)tg;
            }
        }
        __syncwarp();

        float* otags = out + (size_t)b * TT;
#pragma unroll
        for (int c = 0; c < 4; c++) {
            uchar4 u = ((const uchar4*)tags_sm)[c * 32 + lane];
            ((float4*)otags)[c * 32 + lane] =
                make_float4((float)u.x, (float)u.y, (float)u.z, (float)u.w);
        }

        // ---- gold sequence score ----
        const int* ti = tagidx + (size_t)b * TT;
        float acc = 0.f;
        for (int tt = lane; tt < TT; tt += 32) {
            int tg = ti[tt];
            if (tt < len)
                acc += pb[tt * KK + tg];
            if (tt < len - 1)
                acc += trans[tg * KK + ti[tt + 1]];
        }
#pragma unroll
        for (int s = 16; s; s >>= 1)
            acc += __shfl_xor_sync(0xffffffffu, acc, s);

        if (lane == 0) {
            out[(size_t)BB * TT + b]      = mv;               // best_score
            out[(size_t)BB * TT + BB + b] = acc - log_norm;   // log_likelihood
        }
    }
}

extern "C" void kernel_launch(void* const* d_in, const int* in_sizes, int n_in,
                              void* d_out, int out_size) {
    const float* pot = nullptr;
    const float* trn = nullptr;
    const int*   len = nullptr;
    const int*   tgi = nullptr;
    for (int i = 0; i < n_in; i++) {
        switch (in_sizes[i]) {
            case 33554432: pot = (const float*)d_in[i]; break;
            case 1024:     trn = (const float*)d_in[i]; break;
            case 2048:     len = (const int*)d_in[i];   break;
            case 1048576:  tgi = (const int*)d_in[i];   break;
            default: break;
        }
    }
    float* out = (float*)d_out;
    crf_init<<<1, 1>>>();
    crf_kernel<<<NCTA, 32>>>(pot, trn, len, tgi, out);
    (void)out_size;
}

// round 8
// speedup vs baseline: 1.5950x; 1.0313x over previous
#include <cuda_runtime.h>
#include <cuda_bf16.h>

#define BB 2048
#define TT 512
#define KK 32
#define NEG_INF (-3.4e38f)
#define NCTA (148 * 13)

__device__ unsigned g_ctr;

__global__ void crf_init() { g_ctr = 0u; }

// One warp per CTA; warp pulls batch items from a global queue and runs BOTH
// recurrences (Viterbi + forward). Hot loop is fully branch-free (predicated
// selects only) to avoid ptxas BSSY/BSYNC structures around C++ if{}.
__global__ __launch_bounds__(32) void crf_kernel(
    const float* __restrict__ pot,     // [B,T,K]
    const float* __restrict__ trans,   // [K,K]
    const int*   __restrict__ lens,    // [B]
    const int*   __restrict__ tagidx,  // [B,T]
    float*       __restrict__ out)     // [B*T] tags, [B] best, [B] loglik
{
    const int lane = threadIdx.x;

    __shared__ unsigned char bp_sm[TT * KK];
    __shared__ __align__(16) float2 xbuf[2][KK];   // (aV, pexp) interleaved
    __shared__ __align__(16) unsigned char tags_sm[TT];

    // transitions column k (coalesced) + exp — loaded once per block
    float tc[KK], ec[KK];
#pragma unroll
    for (int j = 0; j < KK; j++) {
        float v = trans[j * KK + lane];
        tc[j] = v;
        ec[j] = __expf(v);
    }

    for (;;) {
        unsigned b = 0;
        if (lane == 0) b = atomicAdd(&g_ctr, 1u);
        b = __shfl_sync(0xffffffffu, b, 0);
        if (b >= BB) break;

        const int len = lens[b];
        const float* pb = pot + (size_t)b * (TT * KK);

        float aV = pb[lane];
        float aF = aV;
        float mcur = __shfl_sync(0xffffffffu, aF, 0);

        // prefetch ring, depth 4 (rows 1..4 in-bounds, TT=512)
        float q0 = pb[1 * KK + lane];
        float q1 = pb[2 * KK + lane];
        float q2 = pb[3 * KK + lane];
        float q3 = pb[4 * KK + lane];

        auto step = [&](float pt, int t, int buf) {
            float pexp = __expf(aF - mcur);
            xbuf[buf][lane] = make_float2(aV, pexp);
            __syncwarp();
            const float4* x4 = (const float4*)xbuf[buf];   // 2 j's per float4

            float m0 = NEG_INF, m1 = NEG_INF, m2 = NEG_INF, m3 = NEG_INF;
            int   i0 = 0, i1 = 0, i2 = 0, i3 = 0;
            float s0 = 0.f, s1 = 0.f, s2 = 0.f, s3 = 0.f;
#pragma unroll
            for (int q = 0; q < 8; q++) {
                float4 xa = x4[2 * q];       // j = 4q, 4q+1 : (aV,p,aV,p)
                float4 xb = x4[2 * q + 1];   // j = 4q+2, 4q+3
                float v0 = xa.x + tc[4*q+0];
                float v1 = xa.z + tc[4*q+1];
                float v2 = xb.x + tc[4*q+2];
                float v3 = xb.z + tc[4*q+3];
                bool g0 = v0 > m0; i0 = g0 ? (4*q+0) : i0; m0 = g0 ? v0 : m0;
                bool g1 = v1 > m1; i1 = g1 ? (4*q+1) : i1; m1 = g1 ? v1 : m1;
                bool g2 = v2 > m2; i2 = g2 ? (4*q+2) : i2; m2 = g2 ? v2 : m2;
                bool g3 = v3 > m3; i3 = g3 ? (4*q+3) : i3; m3 = g3 ? v3 : m3;
                s0 += xa.y * ec[4*q+0];
                s1 += xa.w * ec[4*q+1];
                s2 += xb.y * ec[4*q+2];
                s3 += xb.w * ec[4*q+3];
            }
            // cross-chain combine (branch-free; value-tie -> min index,
            // chain c holds indices = c mod 4 so i_c ordering resolves ties)
            float best = m0; int arg = i0;
            bool c1 = (m1 > best) || ((m1 == best) && (i1 < arg));
            arg  = c1 ? i1 : arg;  best = c1 ? m1 : best;
            bool c2 = (m2 > best) || ((m2 == best) && (i2 < arg));
            arg  = c2 ? i2 : arg;  best = c2 ? m2 : best;
            bool c3 = (m3 > best) || ((m3 == best) && (i3 < arg));
            arg  = c3 ? i3 : arg;  best = c3 ? m3 : best;
            float ssum = (s0 + s1) + (s2 + s3);

            bp_sm[t * KK + lane] = (unsigned char)arg;
            aV = pt + best;
            aF = pt + (mcur + __logf(ssum));
            mcur = __shfl_sync(0xffffffffu, aF, 0);   // uniform offset = new aF lane 0
        };

        int t = 1;
        for (; t + 3 < len; t += 4) {
            int c4 = min(t + 4, TT - 1), c5 = min(t + 5, TT - 1);
            int c6 = min(t + 6, TT - 1), c7 = min(t + 7, TT - 1);
            float n0 = pb[c4 * KK + lane];
            float n1 = pb[c5 * KK + lane];
            float n2 = pb[c6 * KK + lane];
            float n3 = pb[c7 * KK + lane];
            step(q0, t + 0, 1);
            step(q1, t + 1, 0);
            step(q2, t + 2, 1);
            step(q3, t + 3, 0);
            q0 = n0; q1 = n1; q2 = n2; q3 = n3;
        }
        if (t < len) { step(q0, t, 1); t++; }
        if (t < len) { step(q1, t, 0); t++; }
        if (t < len) { step(q2, t, 1); }
        __syncwarp();

        // ---- Viterbi terminal: best_score + last_tag (first max index) ----
        float mv = aV;
#pragma unroll
        for (int s = 16; s; s >>= 1)
            mv = fmaxf(mv, __shfl_xor_sync(0xffffffffu, mv, s));
        unsigned msk = __ballot_sync(0xffffffffu, aV == mv);
        int last_tag = __ffs(msk) - 1;

        // ---- exact final logsumexp ----
        float mf = aF;
#pragma unroll
        for (int s = 16; s; s >>= 1)
            mf = fmaxf(mf, __shfl_xor_sync(0xffffffffu, mf, s));
        float ex = __expf(aF - mf);
#pragma unroll
        for (int s = 16; s; s >>= 1)
            ex += __shfl_xor_sync(0xffffffffu, ex, s);
        float log_norm = mf + __logf(ex);

        // ---- tags: fill with last_tag, then backtrace over smem ----
        unsigned rep = (unsigned)last_tag * 0x01010101u;
#pragma unroll
        for (int w = 0; w < 4; w++)
            ((unsigned*)tags_sm)[w * 32 + lane] = rep;
        __syncwarp();

        if (lane == 0) {
            int tg = last_tag;
            for (int tt = len - 1; tt >= 1; tt--) {
                tg = bp_sm[tt * KK + tg];
                tags_sm[tt - 1] = (unsigned char)tg;
            }
        }
        __syncwarp();

        float* otags = out + (size_t)b * TT;
#pragma unroll
        for (int c = 0; c < 4; c++) {
            uchar4 u = ((const uchar4*)tags_sm)[c * 32 + lane];
            ((float4*)otags)[c * 32 + lane] =
                make_float4((float)u.x, (float)u.y, (float)u.z, (float)u.w);
        }

        // ---- gold sequence score (branch-free accumulation) ----
        const int* ti = tagidx + (size_t)b * TT;
        float acc = 0.f;
#pragma unroll 4
        for (int tt = lane; tt < TT; tt += 32) {
            int tg = ti[tt];
            float u  = pb[tt * KK + tg];                       // in-bounds always
            int   tn = ti[min(tt + 1, TT - 1)];
            float w  = trans[tg * KK + tn];
            acc += (tt < len)     ? u : 0.f;
            acc += (tt < len - 1) ? w : 0.f;
        }
#pragma unroll
        for (int s = 16; s; s >>= 1)
            acc += __shfl_xor_sync(0xffffffffu, acc, s);

        if (lane == 0) {
            out[(size_t)BB * TT + b]      = mv;               // best_score
            out[(size_t)BB * TT + BB + b] = acc - log_norm;   // log_likelihood
        }
    }
}

extern "C" void kernel_launch(void* const* d_in, const int* in_sizes, int n_in,
                              void* d_out, int out_size) {
    const float* pot = nullptr;
    const float* trn = nullptr;
    const int*   len = nullptr;
    const int*   tgi = nullptr;
    for (int i = 0; i < n_in; i++) {
        switch (in_sizes[i]) {
            case 33554432: pot = (const float*)d_in[i]; break;
            case 1024:     trn = (const float*)d_in[i]; break;
            case 2048:     len = (const int*)d_in[i];   break;
            case 1048576:  tgi = (const int*)d_in[i];   break;
            default: break;
        }
    }
    float* out = (float*)d_out;
    crf_init<<<1, 1>>>();
    crf_kernel<<<NCTA, 32>>>(pot, trn, len, tgi, out);
    (void)out_size;
}